// round 8
// baseline (speedup 1.0000x reference)
#include <cuda_runtime.h>
#include <cuda_bf16.h>
#include <math_constants.h>

#define DIM 4096
#define CAP 8192
#define VEC (DIM / 4)      // 1024 float4 per row
#define MAXK 64

// Scratch (no allocations allowed)
__device__ float g_scores[CAP];
__device__ float g_retrieved[DIM];

// ---------------------------------------------------------------------------
// Block-wide 3-value sum reduction helper (warp shuffle + smem)
// ---------------------------------------------------------------------------
__device__ __forceinline__ void block_reduce3(float& a, float& b, float& c) {
    __shared__ float sa[8], sb[8], sc[8];
    int lane = threadIdx.x & 31;
    int wid  = threadIdx.x >> 5;
    #pragma unroll
    for (int off = 16; off > 0; off >>= 1) {
        a += __shfl_down_sync(0xffffffffu, a, off);
        b += __shfl_down_sync(0xffffffffu, b, off);
        c += __shfl_down_sync(0xffffffffu, c, off);
    }
    if (lane == 0) { sa[wid] = a; sb[wid] = b; sc[wid] = c; }
    __syncthreads();
    if (wid == 0) {
        int nw = blockDim.x >> 5;
        a = (lane < nw) ? sa[lane] : 0.0f;
        b = (lane < nw) ? sb[lane] : 0.0f;
        c = (lane < nw) ? sc[lane] : 0.0f;
        #pragma unroll
        for (int off = 4; off > 0; off >>= 1) {
            a += __shfl_down_sync(0xffffffffu, a, off);
            b += __shfl_down_sync(0xffffffffu, b, off);
            c += __shfl_down_sync(0xffffffffu, c, off);
        }
    }
}

// ---------------------------------------------------------------------------
// Kernel 1: weighted cosine-similarity scores. One block per memory row.
// (proven: 26.8us, DRAM 64.9%, 32 regs, occ 83%)
// ---------------------------------------------------------------------------
__global__ void __launch_bounds__(256, 8)
scores_kernel(const float* __restrict__ query,
              const float* __restrict__ memory_bank,
              const float* __restrict__ importance,
              const float* __restrict__ age) {
    int row = blockIdx.x;
    const float4* q4 = reinterpret_cast<const float4*>(query);
    const float4* m4 = reinterpret_cast<const float4*>(memory_bank + (size_t)row * DIM);

    float dot = 0.0f, msq = 0.0f, qsq = 0.0f;
    #pragma unroll
    for (int i = 0; i < VEC / 256; i++) {
        int idx = threadIdx.x + (i << 8);
        float4 m = __ldcs(m4 + idx);
        float4 q = q4[idx];
        dot += q.x * m.x + q.y * m.y + q.z * m.z + q.w * m.w;
        msq += m.x * m.x + m.y * m.y + m.z * m.z + m.w * m.w;
        qsq += q.x * q.x + q.y * q.y + q.z * q.z + q.w * q.w;
    }
    block_reduce3(dot, msq, qsq);
    if (threadIdx.x == 0) {
        float denom = fmaxf(sqrtf(qsq) * sqrtf(msq), 1e-8f);
        float sim = dot / denom;
        g_scores[row] = sim * importance[row] * expf(-0.001f * age[row]);
    }
}

// ---------------------------------------------------------------------------
// Kernel 2: top-k + mean pool. Single block. (unchanged from passing R7)
// All __syncthreads() executed unconditionally by all 256 threads.
// Tie-break matches jax.lax.top_k (smaller index wins on equal value).
// ---------------------------------------------------------------------------
__device__ __forceinline__ bool cmp_gt(float av, int ai, float bv, int bi) {
    return (av > bv) || (av == bv && ai < bi);
}

__global__ void __launch_bounds__(256, 1)
topk_mean_kernel(const float* __restrict__ memory_bank,
                 const int* __restrict__ top_k_ptr) {
    __shared__ float s[CAP];                         // 32 KB staged scores
    __shared__ int   chosen[MAXK];
    __shared__ float rv[256];
    __shared__ int   ri[256];

    int tid = threadIdx.x;

    // stage: independent loads -> full MLP
    #pragma unroll
    for (int t = 0; t < CAP / 256; t++) {
        int i = tid + (t << 8);
        s[i] = g_scores[i];
    }
    __syncthreads();

    int k = top_k_ptr[0];
    if (k < 1) k = 1;
    if (k > MAXK) k = MAXK;

    if (k <= 8) {
        // -------- per-thread sorted top-8 from SMEM --------
        float lv[8]; int li[8];
        #pragma unroll
        for (int j = 0; j < 8; j++) { lv[j] = -CUDART_INF_F; li[j] = CAP + j; }

        #pragma unroll 4
        for (int t = 0; t < CAP / 256; t++) {
            int i = tid + (t << 8);          // ascending index order
            float v = s[i];
            if (cmp_gt(v, i, lv[7], li[7])) {
                lv[7] = v; li[7] = i;
                #pragma unroll
                for (int j = 7; j > 0; j--) {
                    if (cmp_gt(lv[j], li[j], lv[j-1], li[j-1])) {
                        float tv = lv[j]; lv[j] = lv[j-1]; lv[j-1] = tv;
                        int   ti = li[j]; li[j] = li[j-1]; li[j-1] = ti;
                    }
                }
            }
        }
        __syncthreads();   // ALL threads: done reading s; safe to alias

        // alias smem: 256 sorted lists of 8 (val 8KB + idx 8KB)
        float (*sv)[8] = reinterpret_cast<float(*)[8]>(s);
        int   (*si)[8] = reinterpret_cast<int(*)[8]>(s + 2048);
        #pragma unroll
        for (int j = 0; j < 8; j++) { sv[tid][j] = lv[j]; si[tid][j] = li[j]; }
        __syncthreads();

        // tree merge 256 -> 1; barriers convergent for all threads
        for (int stride = 128; stride >= 1; stride >>= 1) {
            bool active = (tid < stride);
            float mv[8]; int mi[8];
            if (active) {
                int pa = 0, pb = 0;
                #pragma unroll
                for (int j = 0; j < 8; j++) {
                    float av = sv[tid][pa];          int ai = si[tid][pa];
                    float bv = sv[tid + stride][pb]; int bi = si[tid + stride][pb];
                    if (cmp_gt(av, ai, bv, bi)) { mv[j] = av; mi[j] = ai; pa++; }
                    else                        { mv[j] = bv; mi[j] = bi; pb++; }
                }
            }
            __syncthreads();
            if (active) {
                #pragma unroll
                for (int j = 0; j < 8; j++) { sv[tid][j] = mv[j]; si[tid][j] = mi[j]; }
            }
            __syncthreads();
        }
        if (tid < k) chosen[tid] = si[0][tid];
        __syncthreads();
    } else {
        // -------- fallback: iterative argmax rounds over staged smem --------
        for (int r = 0; r < k; r++) {
            float best = -CUDART_INF_F; int bi = CAP;
            for (int i = tid; i < CAP; i += 256) {
                float v = s[i];
                if (v > best) { best = v; bi = i; }
            }
            rv[tid] = best; ri[tid] = bi;
            __syncthreads();
            for (int off = 128; off > 0; off >>= 1) {
                if (tid < off) {
                    float ov = rv[tid + off]; int oi = ri[tid + off];
                    if (ov > rv[tid] || (ov == rv[tid] && oi < ri[tid])) {
                        rv[tid] = ov; ri[tid] = oi;
                    }
                }
                __syncthreads();
            }
            if (tid == 0) { chosen[r] = ri[0]; s[ri[0]] = -CUDART_INF_F; }
            __syncthreads();
        }
    }

    // mean-pool the k selected rows -> g_retrieved (independent loads, MLP=k)
    float invk = 1.0f / (float)k;
    for (int j = tid; j < VEC; j += 256) {
        float4 acc = make_float4(0.f, 0.f, 0.f, 0.f);
        for (int r = 0; r < k; r++) {
            const float4* row4 =
                reinterpret_cast<const float4*>(memory_bank + (size_t)chosen[r] * DIM);
            float4 v = row4[j];
            acc.x += v.x; acc.y += v.y; acc.z += v.z; acc.w += v.w;
        }
        reinterpret_cast<float4*>(g_retrieved)[j] =
            make_float4(acc.x * invk, acc.y * invk, acc.z * invk, acc.w * invk);
    }
}

// ---------------------------------------------------------------------------
// Kernel 3: out[i] = b[i] + sum_j W[i][j] * retrieved[j].
// Block-per-row, same proven shape as scores (32 regs, 8 blocks/SM).
// ---------------------------------------------------------------------------
__global__ void __launch_bounds__(256, 8)
decode_kernel(const float* __restrict__ W_dec,
              const float* __restrict__ b_dec,
              float* __restrict__ out) {
    int row = blockIdx.x;
    const float4* w4 = reinterpret_cast<const float4*>(W_dec + (size_t)row * DIM);
    const float4* r4 = reinterpret_cast<const float4*>(g_retrieved);

    float acc = 0.0f, d1 = 0.0f, d2 = 0.0f;
    #pragma unroll
    for (int i = 0; i < VEC / 256; i++) {
        int idx = threadIdx.x + (i << 8);
        float4 w = __ldcs(w4 + idx);
        float4 r = r4[idx];
        acc += w.x * r.x + w.y * r.y + w.z * r.z + w.w * r.w;
    }
    block_reduce3(acc, d1, d2);
    if (threadIdx.x == 0) out[row] = acc + b_dec[row];
}

// ---------------------------------------------------------------------------
extern "C" void kernel_launch(void* const* d_in, const int* in_sizes, int n_in,
                              void* d_out, int out_size) {
    const float* query       = (const float*)d_in[0];
    const float* memory_bank = (const float*)d_in[1];
    const float* importance  = (const float*)d_in[2];
    const float* age         = (const float*)d_in[3];
    const float* W_dec       = (const float*)d_in[4];
    const float* b_dec       = (const float*)d_in[5];
    const int*   top_k       = (const int*)d_in[6];
    float* out = (float*)d_out;

    scores_kernel<<<CAP, 256>>>(query, memory_bank, importance, age);
    topk_mean_kernel<<<1, 256>>>(memory_bank, top_k);
    decode_kernel<<<DIM, 256>>>(W_dec, b_dec, out);
}

// round 9
// speedup vs baseline: 1.0135x; 1.0135x over previous
#include <cuda_runtime.h>
#include <cuda_bf16.h>
#include <math_constants.h>

#define DIM 4096
#define CAP 8192
#define VEC (DIM / 4)      // 1024 float4 per row
#define MAXK 64

// Scratch (no allocations allowed)
__device__ float g_scores[CAP];
__device__ float g_retrieved[DIM];

// ---------------------------------------------------------------------------
// Block-wide 3-value sum reduction helper (warp shuffle + smem)
// ---------------------------------------------------------------------------
__device__ __forceinline__ void block_reduce3(float& a, float& b, float& c) {
    __shared__ float sa[8], sb[8], sc[8];
    int lane = threadIdx.x & 31;
    int wid  = threadIdx.x >> 5;
    #pragma unroll
    for (int off = 16; off > 0; off >>= 1) {
        a += __shfl_down_sync(0xffffffffu, a, off);
        b += __shfl_down_sync(0xffffffffu, b, off);
        c += __shfl_down_sync(0xffffffffu, c, off);
    }
    if (lane == 0) { sa[wid] = a; sb[wid] = b; sc[wid] = c; }
    __syncthreads();
    if (wid == 0) {
        int nw = blockDim.x >> 5;
        a = (lane < nw) ? sa[lane] : 0.0f;
        b = (lane < nw) ? sb[lane] : 0.0f;
        c = (lane < nw) ? sc[lane] : 0.0f;
        #pragma unroll
        for (int off = 4; off > 0; off >>= 1) {
            a += __shfl_down_sync(0xffffffffu, a, off);
            b += __shfl_down_sync(0xffffffffu, b, off);
            c += __shfl_down_sync(0xffffffffu, c, off);
        }
    }
}

// ---------------------------------------------------------------------------
// Kernel 1: weighted cosine-similarity scores. One block per memory row.
// (proven: ~26.7us, DRAM 65%). Fires PDL trigger early so topk's launch
// latency is hidden behind the scores stream.
// ---------------------------------------------------------------------------
__global__ void __launch_bounds__(256, 8)
scores_kernel(const float* __restrict__ query,
              const float* __restrict__ memory_bank,
              const float* __restrict__ importance,
              const float* __restrict__ age) {
    cudaTriggerProgrammaticLaunchCompletion();
    int row = blockIdx.x;
    const float4* q4 = reinterpret_cast<const float4*>(query);
    const float4* m4 = reinterpret_cast<const float4*>(memory_bank + (size_t)row * DIM);

    float dot = 0.0f, msq = 0.0f, qsq = 0.0f;
    #pragma unroll
    for (int i = 0; i < VEC / 256; i++) {
        int idx = threadIdx.x + (i << 8);
        float4 m = __ldcs(m4 + idx);
        float4 q = q4[idx];
        dot += q.x * m.x + q.y * m.y + q.z * m.z + q.w * m.w;
        msq += m.x * m.x + m.y * m.y + m.z * m.z + m.w * m.w;
        qsq += q.x * q.x + q.y * q.y + q.z * q.z + q.w * q.w;
    }
    block_reduce3(dot, msq, qsq);
    if (threadIdx.x == 0) {
        float denom = fmaxf(sqrtf(qsq) * sqrtf(msq), 1e-8f);
        float sim = dot / denom;
        g_scores[row] = sim * importance[row] * expf(-0.001f * age[row]);
    }
}

// ---------------------------------------------------------------------------
// Kernel 2: top-k + mean pool. Single block, PDL consumer of scores.
// Waits for scores completion via cudaGridDependencySynchronize, and fires
// its own trigger early so decode's grid can launch + prefetch W_dec.
// Tie-break matches jax.lax.top_k (smaller index wins on equal value).
// ---------------------------------------------------------------------------
__device__ __forceinline__ bool cmp_gt(float av, int ai, float bv, int bi) {
    return (av > bv) || (av == bv && ai < bi);
}

__global__ void __launch_bounds__(256, 1)
topk_mean_kernel(const float* __restrict__ memory_bank,
                 const int* __restrict__ top_k_ptr) {
    __shared__ float s[CAP];                         // 32 KB staged scores
    __shared__ int   chosen[MAXK];
    __shared__ float rv[256];
    __shared__ int   ri[256];

    cudaTriggerProgrammaticLaunchCompletion();   // let decode blocks launch now
    cudaGridDependencySynchronize();             // wait for scores to finish

    int tid = threadIdx.x;

    // stage: independent loads -> full MLP
    #pragma unroll
    for (int t = 0; t < CAP / 256; t++) {
        int i = tid + (t << 8);
        s[i] = g_scores[i];
    }
    __syncthreads();

    int k = top_k_ptr[0];
    if (k < 1) k = 1;
    if (k > MAXK) k = MAXK;

    if (k <= 8) {
        // -------- per-thread sorted top-8 from SMEM --------
        float lv[8]; int li[8];
        #pragma unroll
        for (int j = 0; j < 8; j++) { lv[j] = -CUDART_INF_F; li[j] = CAP + j; }

        #pragma unroll 4
        for (int t = 0; t < CAP / 256; t++) {
            int i = tid + (t << 8);          // ascending index order
            float v = s[i];
            if (cmp_gt(v, i, lv[7], li[7])) {
                lv[7] = v; li[7] = i;
                #pragma unroll
                for (int j = 7; j > 0; j--) {
                    if (cmp_gt(lv[j], li[j], lv[j-1], li[j-1])) {
                        float tv = lv[j]; lv[j] = lv[j-1]; lv[j-1] = tv;
                        int   ti = li[j]; li[j] = li[j-1]; li[j-1] = ti;
                    }
                }
            }
        }
        __syncthreads();   // ALL threads: done reading s; safe to alias

        // alias smem: 256 sorted lists of 8 (val 8KB + idx 8KB)
        float (*sv)[8] = reinterpret_cast<float(*)[8]>(s);
        int   (*si)[8] = reinterpret_cast<int(*)[8]>(s + 2048);
        #pragma unroll
        for (int j = 0; j < 8; j++) { sv[tid][j] = lv[j]; si[tid][j] = li[j]; }
        __syncthreads();

        // tree merge 256 -> 1; barriers convergent for all threads
        for (int stride = 128; stride >= 1; stride >>= 1) {
            bool active = (tid < stride);
            float mv[8]; int mi[8];
            if (active) {
                int pa = 0, pb = 0;
                #pragma unroll
                for (int j = 0; j < 8; j++) {
                    float av = sv[tid][pa];          int ai = si[tid][pa];
                    float bv = sv[tid + stride][pb]; int bi = si[tid + stride][pb];
                    if (cmp_gt(av, ai, bv, bi)) { mv[j] = av; mi[j] = ai; pa++; }
                    else                        { mv[j] = bv; mi[j] = bi; pb++; }
                }
            }
            __syncthreads();
            if (active) {
                #pragma unroll
                for (int j = 0; j < 8; j++) { sv[tid][j] = mv[j]; si[tid][j] = mi[j]; }
            }
            __syncthreads();
        }
        if (tid < k) chosen[tid] = si[0][tid];
        __syncthreads();
    } else {
        // -------- fallback: iterative argmax rounds over staged smem --------
        for (int r = 0; r < k; r++) {
            float best = -CUDART_INF_F; int bi = CAP;
            for (int i = tid; i < CAP; i += 256) {
                float v = s[i];
                if (v > best) { best = v; bi = i; }
            }
            rv[tid] = best; ri[tid] = bi;
            __syncthreads();
            for (int off = 128; off > 0; off >>= 1) {
                if (tid < off) {
                    float ov = rv[tid + off]; int oi = ri[tid + off];
                    if (ov > rv[tid] || (ov == rv[tid] && oi < ri[tid])) {
                        rv[tid] = ov; ri[tid] = oi;
                    }
                }
                __syncthreads();
            }
            if (tid == 0) { chosen[r] = ri[0]; s[ri[0]] = -CUDART_INF_F; }
            __syncthreads();
        }
    }

    // mean-pool the k selected rows -> g_retrieved (independent loads, MLP=k)
    float invk = 1.0f / (float)k;
    for (int j = tid; j < VEC; j += 256) {
        float4 acc = make_float4(0.f, 0.f, 0.f, 0.f);
        for (int r = 0; r < k; r++) {
            const float4* row4 =
                reinterpret_cast<const float4*>(memory_bank + (size_t)chosen[r] * DIM);
            float4 v = row4[j];
            acc.x += v.x; acc.y += v.y; acc.z += v.z; acc.w += v.w;
        }
        reinterpret_cast<float4*>(g_retrieved)[j] =
            make_float4(acc.x * invk, acc.y * invk, acc.z * invk, acc.w * invk);
    }
}

// ---------------------------------------------------------------------------
// Kernel 3: out[i] = b[i] + sum_j W[i][j] * retrieved[j]. PDL consumer.
// Front-loads the W row into registers (independent of topk), THEN waits for
// topk, THEN reads g_retrieved. First-wave DRAM streaming overlaps topk.
// ---------------------------------------------------------------------------
__global__ void __launch_bounds__(256, 6)
decode_kernel(const float* __restrict__ W_dec,
              const float* __restrict__ b_dec,
              float* __restrict__ out) {
    int row = blockIdx.x;
    const float4* w4 = reinterpret_cast<const float4*>(W_dec + (size_t)row * DIM);
    const float4* r4 = reinterpret_cast<const float4*>(g_retrieved);

    // prefetch W row: 4 independent LDG.128 per thread (16KB/block in RF)
    float4 w[4];
    #pragma unroll
    for (int i = 0; i < VEC / 256; i++) {
        w[i] = __ldcs(w4 + threadIdx.x + (i << 8));
    }

    cudaGridDependencySynchronize();   // g_retrieved now valid

    float acc = 0.0f, d1 = 0.0f, d2 = 0.0f;
    #pragma unroll
    for (int i = 0; i < VEC / 256; i++) {
        float4 r = r4[threadIdx.x + (i << 8)];
        acc += w[i].x * r.x + w[i].y * r.y + w[i].z * r.z + w[i].w * r.w;
    }
    block_reduce3(acc, d1, d2);
    if (threadIdx.x == 0) out[row] = acc + b_dec[row];
}

// ---------------------------------------------------------------------------
extern "C" void kernel_launch(void* const* d_in, const int* in_sizes, int n_in,
                              void* d_out, int out_size) {
    const float* query       = (const float*)d_in[0];
    const float* memory_bank = (const float*)d_in[1];
    const float* importance  = (const float*)d_in[2];
    const float* age         = (const float*)d_in[3];
    const float* W_dec       = (const float*)d_in[4];
    const float* b_dec       = (const float*)d_in[5];
    const int*   top_k       = (const int*)d_in[6];
    float* out = (float*)d_out;

    // kernel 1: normal launch
    scores_kernel<<<CAP, 256>>>(query, memory_bank, importance, age);

    // kernels 2+3: programmatic dependent launches (overlap launch + prefetch)
    cudaLaunchAttribute pdl_attr[1];
    pdl_attr[0].id = cudaLaunchAttributeProgrammaticStreamSerialization;
    pdl_attr[0].val.programmaticStreamSerializationAllowed = 1;

    {
        cudaLaunchConfig_t cfg = {};
        cfg.gridDim  = dim3(1, 1, 1);
        cfg.blockDim = dim3(256, 1, 1);
        cfg.attrs    = pdl_attr;
        cfg.numAttrs = 1;
        cudaLaunchKernelEx(&cfg, topk_mean_kernel, memory_bank, top_k);
    }
    {
        cudaLaunchConfig_t cfg = {};
        cfg.gridDim  = dim3(DIM, 1, 1);
        cfg.blockDim = dim3(256, 1, 1);
        cfg.attrs    = pdl_attr;
        cfg.numAttrs = 1;
        cudaLaunchKernelEx(&cfg, decode_kernel, W_dec, b_dec, out);
    }
}

// round 10
// speedup vs baseline: 1.0693x; 1.0551x over previous
#include <cuda_runtime.h>
#include <cuda_bf16.h>
#include <math_constants.h>

#define DIM 4096
#define CAP 8192
#define VEC (DIM / 4)      // 1024 float4 per row
#define MAXK 64

// Scratch (no allocations allowed)
__device__ float g_scores[CAP];
__device__ float g_retrieved[DIM];

// ---------------------------------------------------------------------------
// Block-wide 3-value sum reduction helper (warp shuffle + smem)
// ---------------------------------------------------------------------------
__device__ __forceinline__ void block_reduce3(float& a, float& b, float& c) {
    __shared__ float sa[8], sb[8], sc[8];
    int lane = threadIdx.x & 31;
    int wid  = threadIdx.x >> 5;
    #pragma unroll
    for (int off = 16; off > 0; off >>= 1) {
        a += __shfl_down_sync(0xffffffffu, a, off);
        b += __shfl_down_sync(0xffffffffu, b, off);
        c += __shfl_down_sync(0xffffffffu, c, off);
    }
    if (lane == 0) { sa[wid] = a; sb[wid] = b; sc[wid] = c; }
    __syncthreads();
    if (wid == 0) {
        int nw = blockDim.x >> 5;
        a = (lane < nw) ? sa[lane] : 0.0f;
        b = (lane < nw) ? sb[lane] : 0.0f;
        c = (lane < nw) ? sc[lane] : 0.0f;
        #pragma unroll
        for (int off = 4; off > 0; off >>= 1) {
            a += __shfl_down_sync(0xffffffffu, a, off);
            b += __shfl_down_sync(0xffffffffu, b, off);
            c += __shfl_down_sync(0xffffffffu, c, off);
        }
    }
}

// ---------------------------------------------------------------------------
// Kernel 1: weighted cosine-similarity scores + W_dec L2 prefetch.
// One block per memory row; each block also prefetches its 8KB slice of
// W_dec into L2 (W_dec = 64MB fits in ~126MB L2; the memory_bank stream is
// __ldcs evict-first so it preferentially evicts itself, not W).
// ---------------------------------------------------------------------------
__global__ void __launch_bounds__(256, 8)
scores_kernel(const float* __restrict__ query,
              const float* __restrict__ memory_bank,
              const float* __restrict__ importance,
              const float* __restrict__ age,
              const float* __restrict__ W_dec) {
    cudaTriggerProgrammaticLaunchCompletion();
    int row = blockIdx.x;

    // prefetch this block's 8KB slice of W_dec into L2 (64 lines x 128B)
    const char* wslice = reinterpret_cast<const char*>(W_dec)
                       + (size_t)blockIdx.x * 8192;
    if (threadIdx.x < 64) {
        asm volatile("prefetch.global.L2 [%0];"
                     :: "l"(wslice + (size_t)threadIdx.x * 128));
    }

    const float4* q4 = reinterpret_cast<const float4*>(query);
    const float4* m4 = reinterpret_cast<const float4*>(memory_bank + (size_t)row * DIM);

    float dot = 0.0f, msq = 0.0f, qsq = 0.0f;
    #pragma unroll
    for (int i = 0; i < VEC / 256; i++) {
        int idx = threadIdx.x + (i << 8);
        float4 m = __ldcs(m4 + idx);
        float4 q = q4[idx];
        dot += q.x * m.x + q.y * m.y + q.z * m.z + q.w * m.w;
        msq += m.x * m.x + m.y * m.y + m.z * m.z + m.w * m.w;
        qsq += q.x * q.x + q.y * q.y + q.z * q.z + q.w * q.w;
    }
    block_reduce3(dot, msq, qsq);
    if (threadIdx.x == 0) {
        float denom = fmaxf(sqrtf(qsq) * sqrtf(msq), 1e-8f);
        float sim = dot / denom;
        g_scores[row] = sim * importance[row] * expf(-0.001f * age[row]);
    }
}

// ---------------------------------------------------------------------------
// Kernel 2: top-k + mean pool. Single block, PDL consumer of scores.
// Tie-break matches jax.lax.top_k (smaller index wins on equal value).
// ---------------------------------------------------------------------------
__device__ __forceinline__ bool cmp_gt(float av, int ai, float bv, int bi) {
    return (av > bv) || (av == bv && ai < bi);
}

__global__ void __launch_bounds__(256, 1)
topk_mean_kernel(const float* __restrict__ memory_bank,
                 const int* __restrict__ top_k_ptr) {
    __shared__ float s[CAP];                         // 32 KB staged scores
    __shared__ int   chosen[MAXK];
    __shared__ float rv[256];
    __shared__ int   ri[256];

    cudaTriggerProgrammaticLaunchCompletion();   // let decode blocks launch now
    cudaGridDependencySynchronize();             // wait for scores to finish

    int tid = threadIdx.x;

    // stage: independent loads -> full MLP
    #pragma unroll
    for (int t = 0; t < CAP / 256; t++) {
        int i = tid + (t << 8);
        s[i] = g_scores[i];
    }
    __syncthreads();

    int k = top_k_ptr[0];
    if (k < 1) k = 1;
    if (k > MAXK) k = MAXK;

    if (k <= 8) {
        // -------- per-thread sorted top-8 from SMEM --------
        float lv[8]; int li[8];
        #pragma unroll
        for (int j = 0; j < 8; j++) { lv[j] = -CUDART_INF_F; li[j] = CAP + j; }

        #pragma unroll 4
        for (int t = 0; t < CAP / 256; t++) {
            int i = tid + (t << 8);          // ascending index order
            float v = s[i];
            if (cmp_gt(v, i, lv[7], li[7])) {
                lv[7] = v; li[7] = i;
                #pragma unroll
                for (int j = 7; j > 0; j--) {
                    if (cmp_gt(lv[j], li[j], lv[j-1], li[j-1])) {
                        float tv = lv[j]; lv[j] = lv[j-1]; lv[j-1] = tv;
                        int   ti = li[j]; li[j] = li[j-1]; li[j-1] = ti;
                    }
                }
            }
        }
        __syncthreads();   // ALL threads: done reading s; safe to alias

        // alias smem: 256 sorted lists of 8 (val 8KB + idx 8KB)
        float (*sv)[8] = reinterpret_cast<float(*)[8]>(s);
        int   (*si)[8] = reinterpret_cast<int(*)[8]>(s + 2048);
        #pragma unroll
        for (int j = 0; j < 8; j++) { sv[tid][j] = lv[j]; si[tid][j] = li[j]; }
        __syncthreads();

        // tree merge 256 -> 1; barriers convergent for all threads
        for (int stride = 128; stride >= 1; stride >>= 1) {
            bool active = (tid < stride);
            float mv[8]; int mi[8];
            if (active) {
                int pa = 0, pb = 0;
                #pragma unroll
                for (int j = 0; j < 8; j++) {
                    float av = sv[tid][pa];          int ai = si[tid][pa];
                    float bv = sv[tid + stride][pb]; int bi = si[tid + stride][pb];
                    if (cmp_gt(av, ai, bv, bi)) { mv[j] = av; mi[j] = ai; pa++; }
                    else                        { mv[j] = bv; mi[j] = bi; pb++; }
                }
            }
            __syncthreads();
            if (active) {
                #pragma unroll
                for (int j = 0; j < 8; j++) { sv[tid][j] = mv[j]; si[tid][j] = mi[j]; }
            }
            __syncthreads();
        }
        if (tid < k) chosen[tid] = si[0][tid];
        __syncthreads();
    } else {
        // -------- fallback: iterative argmax rounds over staged smem --------
        for (int r = 0; r < k; r++) {
            float best = -CUDART_INF_F; int bi = CAP;
            for (int i = tid; i < CAP; i += 256) {
                float v = s[i];
                if (v > best) { best = v; bi = i; }
            }
            rv[tid] = best; ri[tid] = bi;
            __syncthreads();
            for (int off = 128; off > 0; off >>= 1) {
                if (tid < off) {
                    float ov = rv[tid + off]; int oi = ri[tid + off];
                    if (ov > rv[tid] || (ov == rv[tid] && oi < ri[tid])) {
                        rv[tid] = ov; ri[tid] = oi;
                    }
                }
                __syncthreads();
            }
            if (tid == 0) { chosen[r] = ri[0]; s[ri[0]] = -CUDART_INF_F; }
            __syncthreads();
        }
    }

    // mean-pool the k selected rows -> g_retrieved (independent loads, MLP=k)
    float invk = 1.0f / (float)k;
    for (int j = tid; j < VEC; j += 256) {
        float4 acc = make_float4(0.f, 0.f, 0.f, 0.f);
        for (int r = 0; r < k; r++) {
            const float4* row4 =
                reinterpret_cast<const float4*>(memory_bank + (size_t)chosen[r] * DIM);
            float4 v = row4[j];
            acc.x += v.x; acc.y += v.y; acc.z += v.z; acc.w += v.w;
        }
        reinterpret_cast<float4*>(g_retrieved)[j] =
            make_float4(acc.x * invk, acc.y * invk, acc.z * invk, acc.w * invk);
    }
}

// ---------------------------------------------------------------------------
// Kernel 3: out[i] = b[i] + sum_j W[i][j] * retrieved[j]. PDL consumer.
// W_dec should now hit L2 (prefetched during scores). Plain loads (no .cs:
// we WANT L2 hits). Front-loads W then waits for topk.
// ---------------------------------------------------------------------------
__global__ void __launch_bounds__(256, 6)
decode_kernel(const float* __restrict__ W_dec,
              const float* __restrict__ b_dec,
              float* __restrict__ out) {
    int row = blockIdx.x;
    const float4* w4 = reinterpret_cast<const float4*>(W_dec + (size_t)row * DIM);
    const float4* r4 = reinterpret_cast<const float4*>(g_retrieved);

    // prefetch W row: 4 independent LDG.128 per thread (L2 hits expected)
    float4 w[4];
    #pragma unroll
    for (int i = 0; i < VEC / 256; i++) {
        w[i] = w4[threadIdx.x + (i << 8)];
    }

    cudaGridDependencySynchronize();   // g_retrieved now valid

    float acc = 0.0f, d1 = 0.0f, d2 = 0.0f;
    #pragma unroll
    for (int i = 0; i < VEC / 256; i++) {
        float4 r = r4[threadIdx.x + (i << 8)];
        acc += w[i].x * r.x + w[i].y * r.y + w[i].z * r.z + w[i].w * r.w;
    }
    block_reduce3(acc, d1, d2);
    if (threadIdx.x == 0) out[row] = acc + b_dec[row];
}

// ---------------------------------------------------------------------------
extern "C" void kernel_launch(void* const* d_in, const int* in_sizes, int n_in,
                              void* d_out, int out_size) {
    const float* query       = (const float*)d_in[0];
    const float* memory_bank = (const float*)d_in[1];
    const float* importance  = (const float*)d_in[2];
    const float* age         = (const float*)d_in[3];
    const float* W_dec       = (const float*)d_in[4];
    const float* b_dec       = (const float*)d_in[5];
    const int*   top_k       = (const int*)d_in[6];
    float* out = (float*)d_out;

    // kernel 1: normal launch (with W_dec prefetch)
    scores_kernel<<<CAP, 256>>>(query, memory_bank, importance, age, W_dec);

    // kernels 2+3: programmatic dependent launches
    cudaLaunchAttribute pdl_attr[1];
    pdl_attr[0].id = cudaLaunchAttributeProgrammaticStreamSerialization;
    pdl_attr[0].val.programmaticStreamSerializationAllowed = 1;

    {
        cudaLaunchConfig_t cfg = {};
        cfg.gridDim  = dim3(1, 1, 1);
        cfg.blockDim = dim3(256, 1, 1);
        cfg.attrs    = pdl_attr;
        cfg.numAttrs = 1;
        cudaLaunchKernelEx(&cfg, topk_mean_kernel, memory_bank, top_k);
    }
    {
        cudaLaunchConfig_t cfg = {};
        cfg.gridDim  = dim3(DIM, 1, 1);
        cfg.blockDim = dim3(256, 1, 1);
        cfg.attrs    = pdl_attr;
        cfg.numAttrs = 1;
        cudaLaunchKernelEx(&cfg, decode_kernel, W_dec, b_dec, out);
    }
}